// round 2
// baseline (speedup 1.0000x reference)
#include <cuda_runtime.h>
#include <cuda_bf16.h>
#include <mma.h>

using namespace nvcuda;

#define BB 2048
#define NN 128
#define DD 512

typedef unsigned long long u64;

// scratch: cw planes [k][b][d], k=0 text-row, k=1 img-row. 8 MB static.
__device__ float g_cw[2 * BB * DD];

__device__ __forceinline__ float tanh_ap(float x) {
    float y;
    asm("tanh.approx.f32 %0, %1;" : "=f"(y) : "f"(x));
    return y;
}
__device__ __forceinline__ u64 ffma2(u64 a, u64 b, u64 c) {
    u64 d;
    asm("fma.rn.f32x2 %0, %1, %2, %3;" : "=l"(d) : "l"(a), "l"(b), "l"(c));
    return d;
}
__device__ __forceinline__ u64 pack2(float lo, float hi) {
    u64 r;
    asm("mov.b64 %0, {%1, %2};" : "=l"(r) : "f"(lo), "f"(hi));
    return r;
}
__device__ __forceinline__ void unpack2(u64 v, float& lo, float& hi) {
    asm("mov.b64 {%0, %1}, %2;" : "=f"(lo), "=f"(hi) : "l"(v));
}
__device__ __forceinline__ void bsplit(float x, __nv_bfloat16& h, __nv_bfloat16& l) {
    __nv_bfloat16 hh = __float2bfloat16(x);
    h = hh;
    l = __float2bfloat16(x - __bfloat162float(hh));
}

// ---------------------------------------------------------------------------
// Kernel A: cw = [text;img] @ cow via bf16 hi/lo split (3 MMAs).
// 128(M) x 64(N) tile, K-chunk 32, 256 threads, register double buffering.
// grid = (DD/64=8, 4096/128=32)
// ---------------------------------------------------------------------------
__global__ __launch_bounds__(256) void cw_gemm(
    const float* __restrict__ text, const float* __restrict__ img,
    const float* __restrict__ cow)
{
    const int rowBase = blockIdx.y * 128;
    const int colBase = blockIdx.x * 64;
    const int tid = threadIdx.x;
    const int warp = tid >> 5;
    const int wm = warp >> 2;          // 0..1  (row group of 64)? no: 8 warps -> 4x2
    const int wmr = warp >> 1;         // 0..3 row warp
    const int wn = warp & 1;           // 0..1 col warp
    (void)wm;

    const float* __restrict__ Abase =
        (rowBase < BB) ? (text + (size_t)rowBase * DD)
                       : (img + (size_t)(rowBase - BB) * DD);

    __shared__ __nv_bfloat16 sAh[128][40], sAl[128][40];
    __shared__ __nv_bfloat16 sBh[32][72], sBl[32][72];

    float4 rA[4], rB[2];

    auto gload = [&](int kc) {
#pragma unroll
        for (int it = 0; it < 4; it++) {
            int q = tid + it * 256;
            int r = q >> 3, c4 = q & 7;
            rA[it] = *(const float4*)(Abase + (size_t)r * DD + kc + c4 * 4);
        }
#pragma unroll
        for (int it = 0; it < 2; it++) {
            int q = tid + it * 256;
            int r = q >> 4, c4 = q & 15;
            rB[it] = *(const float4*)(cow + (size_t)(kc + r) * DD + colBase + c4 * 4);
        }
    };
    auto sstore = [&]() {
#pragma unroll
        for (int it = 0; it < 4; it++) {
            int q = tid + it * 256;
            int r = q >> 3, c4 = q & 7;
            bsplit(rA[it].x, sAh[r][c4*4+0], sAl[r][c4*4+0]);
            bsplit(rA[it].y, sAh[r][c4*4+1], sAl[r][c4*4+1]);
            bsplit(rA[it].z, sAh[r][c4*4+2], sAl[r][c4*4+2]);
            bsplit(rA[it].w, sAh[r][c4*4+3], sAl[r][c4*4+3]);
        }
#pragma unroll
        for (int it = 0; it < 2; it++) {
            int q = tid + it * 256;
            int r = q >> 4, c4 = q & 15;
            bsplit(rB[it].x, sBh[r][c4*4+0], sBl[r][c4*4+0]);
            bsplit(rB[it].y, sBh[r][c4*4+1], sBl[r][c4*4+1]);
            bsplit(rB[it].z, sBh[r][c4*4+2], sBl[r][c4*4+2]);
            bsplit(rB[it].w, sBh[r][c4*4+3], sBl[r][c4*4+3]);
        }
    };

    wmma::fragment<wmma::accumulator, 16, 16, 16, float> acc[2][2];
#pragma unroll
    for (int i = 0; i < 2; i++)
#pragma unroll
        for (int j = 0; j < 2; j++) wmma::fill_fragment(acc[i][j], 0.0f);

    auto compute = [&]() {
#pragma unroll
        for (int ks = 0; ks < 32; ks += 16) {
            wmma::fragment<wmma::matrix_a, 16, 16, 16, __nv_bfloat16, wmma::row_major> ah[2], al[2];
            wmma::fragment<wmma::matrix_b, 16, 16, 16, __nv_bfloat16, wmma::row_major> bh[2], bl[2];
#pragma unroll
            for (int i = 0; i < 2; i++) {
                wmma::load_matrix_sync(ah[i], &sAh[wmr*32 + i*16][ks], 40);
                wmma::load_matrix_sync(al[i], &sAl[wmr*32 + i*16][ks], 40);
                wmma::load_matrix_sync(bh[i], &sBh[ks][wn*32 + i*16], 72);
                wmma::load_matrix_sync(bl[i], &sBl[ks][wn*32 + i*16], 72);
            }
#pragma unroll
            for (int i = 0; i < 2; i++)
#pragma unroll
                for (int j = 0; j < 2; j++) {
                    wmma::mma_sync(acc[i][j], ah[i], bh[j], acc[i][j]);
                    wmma::mma_sync(acc[i][j], ah[i], bl[j], acc[i][j]);
                    wmma::mma_sync(acc[i][j], al[i], bh[j], acc[i][j]);
                }
        }
    };

    gload(0);
    sstore();
    __syncthreads();
    for (int kc = 32; kc < DD; kc += 32) {
        gload(kc);
        compute();
        __syncthreads();
        sstore();
        __syncthreads();
    }
    compute();

    float* C = g_cw + (size_t)rowBase * DD;
#pragma unroll
    for (int i = 0; i < 2; i++)
#pragma unroll
        for (int j = 0; j < 2; j++)
            wmma::store_matrix_sync(
                C + (size_t)(wmr*32 + i*16) * DD + colBase + wn*32 + j*16,
                acc[i][j], DD, wmma::mem_row_major);
}

// ---------------------------------------------------------------------------
// Kernel B: fused co-attention. One CTA per sample, 4 warps.
// Warp w handles row PAIRS (8t+2w, 8t+2w+1). f32x2 packed math.
// ---------------------------------------------------------------------------
__global__ __launch_bounds__(128, 3) void fused_coattn(
    const float* __restrict__ text, const float* __restrict__ img,
    const float* __restrict__ comment, const int* __restrict__ comment_num,
    const float* __restrict__ W_ca, const float* __restrict__ W_co,
    float* __restrict__ out)
{
    const int b = blockIdx.x;
    const int tid = threadIdx.x;
    const int lane = tid & 31;
    const int warp = tid >> 5;
    const int M = comment_num[b];
    const float* __restrict__ comment_b = comment + (size_t)b * NN * DD;

    __shared__ float s_c0[DD], s_c1[DD], s_Wca[DD], s_Wco[DD];
    __shared__ float s_red[4][3 * DD];
    __shared__ float s_mz[4][2];
    __shared__ float s_scalar[8];

    for (int i = tid; i < DD / 4; i += 128) {
        ((float4*)s_c0)[i]  = ((const float4*)(text + (size_t)b * DD))[i];
        ((float4*)s_c1)[i]  = ((const float4*)(img  + (size_t)b * DD))[i];
        ((float4*)s_Wca)[i] = ((const float4*)W_ca)[i];
        ((float4*)s_Wco)[i] = ((const float4*)W_co)[i];
    }
    __syncthreads();

    // packed cw vectors (d = 4*(j*32+lane) + c;  u64 index 2j -> c=0,1; 2j+1 -> c=2,3)
    u64 cw0p[8], cw1p[8];
    {
        const float* cw0g = g_cw + (size_t)b * DD;
        const float* cw1g = g_cw + (size_t)BB * DD + (size_t)b * DD;
#pragma unroll
        for (int j = 0; j < 4; j++) {
            ulonglong2 t0 = *(const ulonglong2*)(cw0g + 4 * (j * 32 + lane));
            ulonglong2 t1 = *(const ulonglong2*)(cw1g + 4 * (j * 32 + lane));
            cw0p[2*j] = t0.x; cw0p[2*j+1] = t0.y;
            cw1p[2*j] = t1.x; cw1p[2*j+1] = t1.y;
        }
    }

    u64 acc0p[8], acc1p[8], aap[8];
#pragma unroll
    for (int i = 0; i < 8; i++) { acc0p[i] = 0ull; acc1p[i] = 0ull; aap[i] = 0ull; }
    float mrun = -3.402823466e38f, Zrun = 0.f;

    u64 zna[8], znb[8], zap[8], zbp[8];

    // row loader: zeros if r >= M
    auto loadrow = [&](int r, u64* zp) {
        if (r < M) {
            const float4* p = (const float4*)(comment_b + (size_t)r * DD);
#pragma unroll
            for (int j = 0; j < 4; j++) {
                float4 t = __ldcs(p + j * 32 + lane);
                zp[2*j] = pack2(t.x, t.y);
                zp[2*j+1] = pack2(t.z, t.w);
            }
        } else {
#pragma unroll
            for (int i = 0; i < 8; i++) zp[i] = 0ull;
        }
    };

    loadrow(2 * warp, zna);
    loadrow(2 * warp + 1, znb);

    for (int base = 2 * warp; base < M; base += 8) {
#pragma unroll
        for (int i = 0; i < 8; i++) { zap[i] = zna[i]; zbp[i] = znb[i]; }
        const bool vb = (base + 1 < M);

        if (base + 8 < M) {
            loadrow(base + 8, zna);
            loadrow(base + 9, znb);
        }

        // dots: 4 packed accumulators
        u64 p0a = 0ull, p1a = 0ull, p0b = 0ull, p1b = 0ull;
#pragma unroll
        for (int i = 0; i < 8; i++) {
            p0a = ffma2(cw0p[i], zap[i], p0a);
            p1a = ffma2(cw1p[i], zap[i], p1a);
            p0b = ffma2(cw0p[i], zbp[i], p0b);
            p1b = ffma2(cw1p[i], zbp[i], p1b);
        }
        float x, y, s0a, s1a, s0b, s1b;
        unpack2(p0a, x, y); s0a = x + y;
        unpack2(p1a, x, y); s1a = x + y;
        unpack2(p0b, x, y); s0b = x + y;
        unpack2(p1b, x, y); s1b = x + y;
#pragma unroll
        for (int o = 16; o; o >>= 1) {
            s0a += __shfl_xor_sync(0xffffffffu, s0a, o);
            s1a += __shfl_xor_sync(0xffffffffu, s1a, o);
            s0b += __shfl_xor_sync(0xffffffffu, s0b, o);
            s1b += __shfl_xor_sync(0xffffffffu, s1b, o);
        }
        const u64 w0ap = pack2(tanh_ap(s0a), tanh_ap(s0a));
        const u64 w1ap = pack2(tanh_ap(s1a), tanh_ap(s1a));
        const u64 w0bp = pack2(tanh_ap(s0b), tanh_ap(s0b));
        const u64 w1bp = pack2(tanh_ap(s1b), tanh_ap(s1b));

        // accumulate co_w*z and comment logits
        u64 lpa = 0ull, lpb = 0ull;
#pragma unroll
        for (int j = 0; j < 4; j++) {
            const int off = 4 * (j * 32 + lane);
            ulonglong2 c0v = *(const ulonglong2*)(s_c0 + off);
            ulonglong2 c1v = *(const ulonglong2*)(s_c1 + off);
            ulonglong2 wv  = *(const ulonglong2*)(s_Wco + off);
#pragma unroll
            for (int h = 0; h < 2; h++) {
                const int i = 2 * j + h;
                const u64 c0 = h ? c0v.y : c0v.x;
                const u64 c1 = h ? c1v.y : c1v.x;
                const u64 wc = h ? wv.y  : wv.x;
                acc0p[i] = ffma2(w0ap, zap[i], acc0p[i]);
                acc1p[i] = ffma2(w1ap, zap[i], acc1p[i]);
                u64 va = ffma2(w0ap, c0, ffma2(w1ap, c1, zap[i]));
                unpack2(va, x, y);
                lpa = ffma2(pack2(tanh_ap(x), tanh_ap(y)), wc, lpa);

                acc0p[i] = ffma2(w0bp, zbp[i], acc0p[i]);
                acc1p[i] = ffma2(w1bp, zbp[i], acc1p[i]);
                u64 vb2 = ffma2(w0bp, c0, ffma2(w1bp, c1, zbp[i]));
                unpack2(vb2, x, y);
                lpb = ffma2(pack2(tanh_ap(x), tanh_ap(y)), wc, lpb);
            }
        }
        float la, lb;
        unpack2(lpa, x, y); la = x + y;
        unpack2(lpb, x, y); lb = x + y;
#pragma unroll
        for (int o = 16; o; o >>= 1) {
            la += __shfl_xor_sync(0xffffffffu, la, o);
            lb += __shfl_xor_sync(0xffffffffu, lb, o);
        }

        // online softmax, row a (always valid)
        if (la <= mrun) {
            float p = __expf(la - mrun);
            Zrun += p;
            u64 pp = pack2(p, p);
#pragma unroll
            for (int i = 0; i < 8; i++) aap[i] = ffma2(pp, zap[i], aap[i]);
        } else {
            float sc = __expf(mrun - la);
            Zrun = fmaf(Zrun, sc, 1.f);
            u64 scp = pack2(sc, sc);
#pragma unroll
            for (int i = 0; i < 8; i++) aap[i] = ffma2(scp, aap[i], zap[i]);
            mrun = la;
        }
        // row b
        if (vb) {
            if (lb <= mrun) {
                float p = __expf(lb - mrun);
                Zrun += p;
                u64 pp = pack2(p, p);
#pragma unroll
                for (int i = 0; i < 8; i++) aap[i] = ffma2(pp, zbp[i], aap[i]);
            } else {
                float sc = __expf(mrun - lb);
                Zrun = fmaf(Zrun, sc, 1.f);
                u64 scp = pack2(sc, sc);
#pragma unroll
                for (int i = 0; i < 8; i++) aap[i] = ffma2(scp, aap[i], zbp[i]);
                mrun = lb;
            }
        }
    }

    // spill per-warp partials
#pragma unroll
    for (int j = 0; j < 4; j++) {
        const int off = 4 * (j * 32 + lane);
        *(ulonglong2*)(s_red[warp] + off)          = make_ulonglong2(acc0p[2*j], acc0p[2*j+1]);
        *(ulonglong2*)(s_red[warp] + DD + off)     = make_ulonglong2(acc1p[2*j], acc1p[2*j+1]);
        *(ulonglong2*)(s_red[warp] + 2*DD + off)   = make_ulonglong2(aap[2*j],   aap[2*j+1]);
    }
    if (lane == 0) { s_mz[warp][0] = mrun; s_mz[warp][1] = Zrun; }
    __syncthreads();

    // cross-warp combine; thread t owns d = 4t..4t+3
    float mg = s_mz[0][0];
#pragma unroll
    for (int w = 1; w < 4; w++) mg = fmaxf(mg, s_mz[w][0]);
    float Zg = 0.f, coef[4];
#pragma unroll
    for (int w = 0; w < 4; w++) {
        coef[w] = __expf(s_mz[w][0] - mg);
        Zg = fmaf(s_mz[w][1], coef[w], Zg);
    }
    float invZ = 1.f / Zg;

    float a0[4] = {0,0,0,0}, a1[4] = {0,0,0,0}, av[4] = {0,0,0,0};
#pragma unroll
    for (int w = 0; w < 4; w++) {
        float4 x0 = *(const float4*)(s_red[w] + 4*tid);
        float4 x1 = *(const float4*)(s_red[w] + DD + 4*tid);
        float4 xa = *(const float4*)(s_red[w] + 2*DD + 4*tid);
        a0[0]+=x0.x; a0[1]+=x0.y; a0[2]+=x0.z; a0[3]+=x0.w;
        a1[0]+=x1.x; a1[1]+=x1.y; a1[2]+=x1.z; a1[3]+=x1.w;
        av[0]=fmaf(xa.x,coef[w],av[0]); av[1]=fmaf(xa.y,coef[w],av[1]);
        av[2]=fmaf(xa.z,coef[w],av[2]); av[3]=fmaf(xa.w,coef[w],av[3]);
    }

    float4 c0v = *(const float4*)(s_c0 + 4*tid);
    float4 c1v = *(const float4*)(s_c1 + 4*tid);
    float4 wca = *(const float4*)(s_Wca + 4*tid);
    float cl0 = tanh_ap(c0v.x + a0[0]) * wca.x + tanh_ap(c0v.y + a0[1]) * wca.y
              + tanh_ap(c0v.z + a0[2]) * wca.z + tanh_ap(c0v.w + a0[3]) * wca.w;
    float cl1 = tanh_ap(c1v.x + a1[0]) * wca.x + tanh_ap(c1v.y + a1[1]) * wca.y
              + tanh_ap(c1v.z + a1[2]) * wca.z + tanh_ap(c1v.w + a1[3]) * wca.w;
#pragma unroll
    for (int o = 16; o; o >>= 1) {
        cl0 += __shfl_xor_sync(0xffffffffu, cl0, o);
        cl1 += __shfl_xor_sync(0xffffffffu, cl1, o);
    }
    if (lane == 0) { s_scalar[warp] = cl0; s_scalar[4 + warp] = cl1; }
    __syncthreads();
    cl0 = s_scalar[0] + s_scalar[1] + s_scalar[2] + s_scalar[3];
    cl1 = s_scalar[4] + s_scalar[5] + s_scalar[6] + s_scalar[7];

    float mx = fmaxf(cl0, cl1);
    float e0 = __expf(cl0 - mx), e1 = __expf(cl1 - mx);
    float einv = 1.f / (e0 + e1);
    float wc0 = e0 * einv, wc1 = e1 * einv;

    float4 o1;
    o1.x = fmaf(c0v.x, wc0, c1v.x * wc1);
    o1.y = fmaf(c0v.y, wc0, c1v.y * wc1);
    o1.z = fmaf(c0v.z, wc0, c1v.z * wc1);
    o1.w = fmaf(c0v.w, wc0, c1v.w * wc1);
    *(float4*)(out + (size_t)b * DD + 4*tid) = o1;

    float4 o2 = make_float4(av[0]*invZ, av[1]*invZ, av[2]*invZ, av[3]*invZ);
    *(float4*)(out + (size_t)BB * DD + (size_t)b * DD + 4*tid) = o2;

    if (tid == 0) {
        out[(size_t)2 * BB * DD + (size_t)b * 2 + 0] = wc0;
        out[(size_t)2 * BB * DD + (size_t)b * 2 + 1] = wc1;
    }
}

extern "C" void kernel_launch(void* const* d_in, const int* in_sizes, int n_in,
                              void* d_out, int out_size)
{
    (void)in_sizes; (void)n_in; (void)out_size;
    const float* text        = (const float*)d_in[0];
    const float* img         = (const float*)d_in[1];
    const float* comment     = (const float*)d_in[2];
    const int*   comment_num = (const int*)d_in[3];
    const float* cow         = (const float*)d_in[4];
    const float* W_ca        = (const float*)d_in[5];
    const float* W_co        = (const float*)d_in[7];
    float* out = (float*)d_out;

    dim3 gg(DD / 64, 4096 / 128);
    cw_gemm<<<gg, 256>>>(text, img, cow);
    fused_coattn<<<BB, 128>>>(text, img, comment, comment_num, W_ca, W_co, out);
}